// round 2
// baseline (speedup 1.0000x reference)
#include <cuda_runtime.h>
#include <cuda_fp16.h>
#include <stdint.h>

// ============================================================================
// out[b,o] = sum_{i,f} norm(sin(w_f x[b,i] + p_f)) * beta[f,o] * lamb[i,o] + bias[o]
// == GEMM: Z[b,k] @ W[k,o],  k = f*512 + i
//   Z[b,k] = sin(w_f * x[b,i] + p_f)          (fp16, generated on the fly)
//   W[k,o] = a_f * beta[f,o] * lamb[i,o]      (fp16, precomputed once)
//   bias'[o] = bias[o] + (sum_f c_f beta[f,o]) * (sum_i lamb[i,o])
// a_f = 1/sqrt(eps+var_f), c_f = -mean_f*a_f.
// tcgen05 is NOT available (ptxas target is sm_103 base, not sm_103a), so this
// uses mma.sync.m16n8k16 (HMMA) + ldmatrix + cp.async.
// ============================================================================

#define EPS_F 1e-3f
#define B_SZ 8192
#define I_SZ 512
#define F_SZ 64
#define O_SZ 512
#define K_SZ 32768

#define BM 128
#define BN 256
#define BK 64
#define NTH 256
#define NITER 512   // K_SZ / BK

// SMEM layout (bytes). Rows are 128B (64 fp16) wide, SW128-swizzled.
#define SM_A 0          // 2 stages x 128 x 128B = 32768
#define SM_B 32768      // 2 stages x 256 x 128B = 65536
#define SM_X 98304      // 128 rows x 64 f32     = 32768
#define SM_TOTAL 131072

__device__ __half g_W[(size_t)O_SZ * K_SZ];   // [O][K], K contiguous (33.5 MB)
__device__ float  g_af[F_SZ];
__device__ float  g_cf[F_SZ];
__device__ float  g_bias[O_SZ];

#define SWZ(o) ((o) ^ (((o) >> 3) & 0x70))

__device__ __forceinline__ uint32_t smem_u32(const void* p) {
    return (uint32_t)__cvta_generic_to_shared(p);
}

__device__ __forceinline__ void ldsm_x4(uint32_t& r0, uint32_t& r1, uint32_t& r2,
                                        uint32_t& r3, uint32_t addr) {
    asm volatile("ldmatrix.sync.aligned.m8n8.x4.shared.b16 {%0,%1,%2,%3}, [%4];"
                 : "=r"(r0), "=r"(r1), "=r"(r2), "=r"(r3) : "r"(addr));
}

__device__ __forceinline__ void mma16816(float* c, const uint32_t* a, const uint32_t* b) {
    asm volatile(
        "mma.sync.aligned.m16n8k16.row.col.f32.f16.f16.f32 "
        "{%0,%1,%2,%3}, {%4,%5,%6,%7}, {%8,%9}, {%0,%1,%2,%3};"
        : "+f"(c[0]), "+f"(c[1]), "+f"(c[2]), "+f"(c[3])
        : "r"(a[0]), "r"(a[1]), "r"(a[2]), "r"(a[3]), "r"(b[0]), "r"(b[1]));
}

// ---------------------------------------------------------------- precompute
__global__ void prep_consts(const float* __restrict__ freqs, const float* __restrict__ phases) {
    int f = threadIdx.x;
    if (f < F_SZ) {
        float w = freqs[f], p = phases[f];
        float mean = expf(-0.5f * w * w) * sinf(p);
        float var  = 0.5f - 0.5f * expf(-2.0f * w * w) * cosf(2.0f * p) - mean * mean;
        float inv  = rsqrtf(EPS_F + var);
        g_af[f] = inv;
        g_cf[f] = -mean * inv;
    }
}

__global__ void build_w(const float* __restrict__ beta, const float* __restrict__ lamb) {
    __shared__ float sl[I_SZ];
    __shared__ float sbv[F_SZ];
    int o = blockIdx.x;
    for (int i = threadIdx.x; i < I_SZ; i += blockDim.x) sl[i] = lamb[i * O_SZ + o];
    if (threadIdx.x < F_SZ)
        sbv[threadIdx.x] = g_af[threadIdx.x] * beta[threadIdx.x * O_SZ + o];
    __syncthreads();
    __half* wrow = g_W + (size_t)o * K_SZ;
    for (int k = threadIdx.x; k < K_SZ; k += blockDim.x) {
        int f = k >> 9, i = k & 511;
        wrow[k] = __float2half_rn(sbv[f] * sl[i]);
    }
}

__global__ void build_bias(const float* __restrict__ beta, const float* __restrict__ lamb,
                           const float* __restrict__ bias) {
    int o = blockIdx.x * blockDim.x + threadIdx.x;
    if (o < O_SZ) {
        float slm = 0.0f;
        for (int i = 0; i < I_SZ; i++) slm += lamb[i * O_SZ + o];
        float scb = 0.0f;
        for (int f = 0; f < F_SZ; f++) scb += g_cf[f] * beta[f * O_SZ + o];
        g_bias[o] = bias[o] + slm * scb;
    }
}

// ---------------------------------------------------------------- main GEMM
__global__ __launch_bounds__(NTH, 1)
void act_gemm(const float* __restrict__ x, const float* __restrict__ freqs,
              const float* __restrict__ phases, float* __restrict__ out) {
    extern __shared__ char smem[];
    const uint32_t sb = smem_u32(smem);
    const int tid  = threadIdx.x;
    const int wid  = tid >> 5;
    const int lane = tid & 31;
    const int wm = (wid & 1) * 64;   // warp M offset within CTA tile
    const int wn = (wid >> 1) * 64;  // warp N offset

    const int n0 = blockIdx.x * BN;
    const int b0 = blockIdx.y * BM;

    float c[4][8][4];
    #pragma unroll
    for (int i = 0; i < 4; i++)
        #pragma unroll
        for (int j = 0; j < 8; j++)
            c[i][j][0] = c[i][j][1] = c[i][j][2] = c[i][j][3] = 0.0f;

    // ---- helper lambdas ------------------------------------------------
    auto load_x = [&](int ic) {
        #pragma unroll
        for (int j = 0; j < 8; j++) {
            int idx4 = tid + j * NTH;           // 2048 float4
            int m = idx4 >> 4, q = idx4 & 15;
            float4 v = *reinterpret_cast<const float4*>(
                x + (size_t)(b0 + m) * I_SZ + ic * BK + q * 4);
            *reinterpret_cast<float4*>(smem + SM_X + m * 256 + q * 16) = v;
        }
    };

    auto issue_b = [&](int t) {                  // cp.async W tile for k-tile t
        const int f = t & 63, ic = t >> 6;
        const int kbase = f * I_SZ + ic * BK;
        const uint32_t bdst = sb + SM_B + (t & 1) * 32768;
        #pragma unroll
        for (int j = 0; j < 8; j++) {
            int idx = tid + j * NTH;             // 2048 x 16B
            int n = idx >> 3, seg = idx & 7;
            const __half* src = g_W + (size_t)(n0 + n) * K_SZ + kbase + seg * 8;
            uint32_t dst = bdst + SWZ(n * 128 + seg * 16);
            asm volatile("cp.async.cg.shared.global [%0], [%1], 16;" :: "r"(dst), "l"(src));
        }
        asm volatile("cp.async.commit_group;" ::: "memory");
    };

    auto gen_a = [&](int t) {                    // Z tile (sines) for k-tile t
        const int f = t & 63;
        const float w = __ldg(freqs + f);
        const float p = __ldg(phases + f);
        const uint32_t adst = sb + SM_A + (t & 1) * 16384;
        #pragma unroll
        for (int j = 0; j < 8; j++) {
            int g = tid + j * NTH;               // 2048 groups of 4 cols
            int m = g >> 4, kg = g & 15;
            float4 xv = *reinterpret_cast<const float4*>(smem + SM_X + m * 256 + kg * 16);
            float s0 = __sinf(fmaf(w, xv.x, p));
            float s1 = __sinf(fmaf(w, xv.y, p));
            float s2 = __sinf(fmaf(w, xv.z, p));
            float s3 = __sinf(fmaf(w, xv.w, p));
            __half2 h0 = __floats2half2_rn(s0, s1);
            __half2 h1 = __floats2half2_rn(s2, s3);
            uint32_t dst = adst + SWZ(m * 128 + kg * 8);
            asm volatile("st.shared.v2.b32 [%0], {%1, %2};"
                         :: "r"(dst), "r"(*(uint32_t*)&h0), "r"(*(uint32_t*)&h1));
        }
    };

    // ---- prologue ------------------------------------------------------
    load_x(0);
    __syncthreads();
    issue_b(0);
    gen_a(0);

    // precomputed ldmatrix lane-address components
    const int a_row = (lane & 15);             // + wm + mt*16
    const int a_kb  = (lane >> 4) << 4;        // + ks*32
    const int b_row = ((lane >> 4) << 3) + (lane & 7);   // + wn + np*16
    const int b_kb  = ((lane >> 3) & 1) << 4;            // + ks*32

    // ---- mainloop ------------------------------------------------------
    for (int t = 0; t < NITER; t++) {
        const int s = t & 1;
        asm volatile("cp.async.wait_group 0;" ::: "memory");
        __syncthreads();    // stage s fully ready; stage s^1 free

        if (((t + 1) & 63) == 0 && t + 1 < NITER) {   // new i-chunk
            load_x((t + 1) >> 6);
            __syncthreads();
        }
        if (t + 1 < NITER) {
            issue_b(t + 1);
            gen_a(t + 1);
        } else {
            asm volatile("cp.async.commit_group;" ::: "memory");  // keep wait balanced
        }

        const uint32_t sA = sb + SM_A + s * 16384;
        const uint32_t sB = sb + SM_B + s * 32768;

        #pragma unroll
        for (int ks = 0; ks < 4; ks++) {
            uint32_t a[4][4], b[8][2];
            #pragma unroll
            for (int mt = 0; mt < 4; mt++) {
                uint32_t addr = sA + SWZ((wm + mt * 16 + a_row) * 128 + ks * 32 + a_kb);
                ldsm_x4(a[mt][0], a[mt][1], a[mt][2], a[mt][3], addr);
            }
            #pragma unroll
            for (int np = 0; np < 4; np++) {
                uint32_t addr = sB + SWZ((wn + np * 16 + b_row) * 128 + ks * 32 + b_kb);
                ldsm_x4(b[np * 2][0], b[np * 2][1], b[np * 2 + 1][0], b[np * 2 + 1][1], addr);
            }
            #pragma unroll
            for (int mt = 0; mt < 4; mt++)
                #pragma unroll
                for (int nt = 0; nt < 8; nt++)
                    mma16816(c[mt][nt], a[mt], b[nt]);
        }
    }

    // ---- epilogue ------------------------------------------------------
    const int r0 = lane >> 2;          // row within 16-row tile (0-7)
    const int c0 = (lane & 3) * 2;     // col pair within 8-col tile
    #pragma unroll
    for (int nt = 0; nt < 8; nt++) {
        const int col = n0 + wn + nt * 8 + c0;
        const float bz0 = __ldg(g_bias + col);
        const float bz1 = __ldg(g_bias + col + 1);
        #pragma unroll
        for (int mt = 0; mt < 4; mt++) {
            const int row = b0 + wm + mt * 16 + r0;
            float2 v0 = make_float2(c[mt][nt][0] + bz0, c[mt][nt][1] + bz1);
            float2 v1 = make_float2(c[mt][nt][2] + bz0, c[mt][nt][3] + bz1);
            *reinterpret_cast<float2*>(out + (size_t)row * O_SZ + col) = v0;
            *reinterpret_cast<float2*>(out + (size_t)(row + 8) * O_SZ + col) = v1;
        }
    }
}

// ---------------------------------------------------------------- launch
extern "C" void kernel_launch(void* const* d_in, const int* in_sizes, int n_in,
                              void* d_out, int out_size) {
    (void)in_sizes; (void)n_in; (void)out_size;
    const float* x      = (const float*)d_in[0];
    const float* freqs  = (const float*)d_in[1];
    const float* phases = (const float*)d_in[2];
    const float* beta   = (const float*)d_in[3];
    const float* lamb   = (const float*)d_in[4];
    const float* bias   = (const float*)d_in[5];
    float* out = (float*)d_out;

    prep_consts<<<1, 64>>>(freqs, phases);
    build_w<<<O_SZ, 256>>>(beta, lamb);
    build_bias<<<2, 256>>>(beta, lamb, bias);

    static int attr_set = 0;
    cudaFuncSetAttribute(act_gemm, cudaFuncAttributeMaxDynamicSharedMemorySize, SM_TOTAL);
    (void)attr_set;

    dim3 grid(O_SZ / BN, B_SZ / BM);  // (2, 64) = 128 CTAs
    act_gemm<<<grid, NTH, SM_TOTAL>>>(x, freqs, phases, out);
}

// round 5
// speedup vs baseline: 1.0632x; 1.0632x over previous
#include <cuda_runtime.h>
#include <cuda_fp16.h>
#include <stdint.h>

// ============================================================================
// out[b,o] = sum_{i,f} norm(sin(w_f x[b,i] + p_f)) * beta[f,o] * lamb[i,o] + bias[o]
// == GEMM: Z[b,k] @ W[k,o],  k = f*512 + i
//   Z[b,k] = sin(w_f * x[b,i] + p_f)          (fp16, generated on the fly)
//   W[k,o] = a_f * beta[f,o] * lamb[i,o]      (fp16, precomputed once)
//   bias'[o] = bias[o] + (sum_f c_f beta[f,o]) * (sum_i lamb[i,o])
// HMMA (mma.sync.m16n8k16) path — tcgen05 unavailable at target sm_103 base.
// R3: BN 256->128, smem 131->96KB, __launch_bounds__(256,2) => 2 CTAs/SM.
// ============================================================================

#define EPS_F 1e-3f
#define B_SZ 8192
#define I_SZ 512
#define F_SZ 64
#define O_SZ 512
#define K_SZ 32768

#define BM 128
#define BN 128
#define BK 64
#define NTH 256
#define NITER 512   // K_SZ / BK

// SMEM layout (bytes). Rows are 128B (64 fp16) wide, SW128-swizzled.
#define SM_A 0          // 2 stages x 128 x 128B = 32768
#define SM_B 32768      // 2 stages x 128 x 128B = 32768
#define SM_X 65536      // 128 rows x 64 f32     = 32768
#define SM_TOTAL 98304

__device__ __half g_W[(size_t)O_SZ * K_SZ];   // [O][K], K contiguous (33.5 MB)
__device__ float  g_af[F_SZ];
__device__ float  g_cf[F_SZ];
__device__ float  g_bias[O_SZ];

#define SWZ(o) ((o) ^ (((o) >> 3) & 0x70))

__device__ __forceinline__ uint32_t smem_u32(const void* p) {
    return (uint32_t)__cvta_generic_to_shared(p);
}

__device__ __forceinline__ void ldsm_x4(uint32_t& r0, uint32_t& r1, uint32_t& r2,
                                        uint32_t& r3, uint32_t addr) {
    asm volatile("ldmatrix.sync.aligned.m8n8.x4.shared.b16 {%0,%1,%2,%3}, [%4];"
                 : "=r"(r0), "=r"(r1), "=r"(r2), "=r"(r3) : "r"(addr));
}

__device__ __forceinline__ void mma16816(float* c, const uint32_t* a, const uint32_t* b) {
    asm volatile(
        "mma.sync.aligned.m16n8k16.row.col.f32.f16.f16.f32 "
        "{%0,%1,%2,%3}, {%4,%5,%6,%7}, {%8,%9}, {%0,%1,%2,%3};"
        : "+f"(c[0]), "+f"(c[1]), "+f"(c[2]), "+f"(c[3])
        : "r"(a[0]), "r"(a[1]), "r"(a[2]), "r"(a[3]), "r"(b[0]), "r"(b[1]));
}

// ---------------------------------------------------------------- precompute
__global__ void prep_consts(const float* __restrict__ freqs, const float* __restrict__ phases) {
    int f = threadIdx.x;
    if (f < F_SZ) {
        float w = freqs[f], p = phases[f];
        float mean = expf(-0.5f * w * w) * sinf(p);
        float var  = 0.5f - 0.5f * expf(-2.0f * w * w) * cosf(2.0f * p) - mean * mean;
        float inv  = rsqrtf(EPS_F + var);
        g_af[f] = inv;
        g_cf[f] = -mean * inv;
    }
}

__global__ void build_w(const float* __restrict__ beta, const float* __restrict__ lamb) {
    __shared__ float sl[I_SZ];
    __shared__ float sbv[F_SZ];
    int o = blockIdx.x;
    for (int i = threadIdx.x; i < I_SZ; i += blockDim.x) sl[i] = lamb[i * O_SZ + o];
    if (threadIdx.x < F_SZ)
        sbv[threadIdx.x] = g_af[threadIdx.x] * beta[threadIdx.x * O_SZ + o];
    __syncthreads();
    __half* wrow = g_W + (size_t)o * K_SZ;
    for (int k = threadIdx.x; k < K_SZ; k += blockDim.x) {
        int f = k >> 9, i = k & 511;
        wrow[k] = __float2half_rn(sbv[f] * sl[i]);
    }
}

__global__ void build_bias(const float* __restrict__ beta, const float* __restrict__ lamb,
                           const float* __restrict__ bias) {
    int o = blockIdx.x * blockDim.x + threadIdx.x;
    if (o < O_SZ) {
        float slm = 0.0f;
        for (int i = 0; i < I_SZ; i++) slm += lamb[i * O_SZ + o];
        float scb = 0.0f;
        for (int f = 0; f < F_SZ; f++) scb += g_cf[f] * beta[f * O_SZ + o];
        g_bias[o] = bias[o] + slm * scb;
    }
}

// ---------------------------------------------------------------- main GEMM
__global__ __launch_bounds__(NTH, 2)
void act_gemm(const float* __restrict__ x, const float* __restrict__ freqs,
              const float* __restrict__ phases, float* __restrict__ out) {
    extern __shared__ char smem[];
    const uint32_t sb = smem_u32(smem);
    const int tid  = threadIdx.x;
    const int wid  = tid >> 5;
    const int lane = tid & 31;
    const int wm = (wid & 1) * 64;   // warp M offset within CTA tile (2 x 64)
    const int wn = (wid >> 1) * 32;  // warp N offset (4 x 32)

    const int n0 = blockIdx.x * BN;
    const int b0 = blockIdx.y * BM;

    // accumulators: 4 m16 tiles x 4 n8 tiles
    float c[4][4][4];
    #pragma unroll
    for (int i = 0; i < 4; i++)
        #pragma unroll
        for (int j = 0; j < 4; j++)
            c[i][j][0] = c[i][j][1] = c[i][j][2] = c[i][j][3] = 0.0f;

    auto load_x = [&](int ic) {
        #pragma unroll
        for (int j = 0; j < 8; j++) {
            int idx4 = tid + j * NTH;           // 2048 float4
            int m = idx4 >> 4, q = idx4 & 15;
            float4 v = *reinterpret_cast<const float4*>(
                x + (size_t)(b0 + m) * I_SZ + ic * BK + q * 4);
            *reinterpret_cast<float4*>(smem + SM_X + m * 256 + q * 16) = v;
        }
    };

    auto issue_b = [&](int t) {                  // cp.async W tile for k-tile t
        const int f = t & 63, ic = t >> 6;
        const int kbase = f * I_SZ + ic * BK;
        const uint32_t bdst = sb + SM_B + (t & 1) * 16384;
        #pragma unroll
        for (int j = 0; j < 4; j++) {
            int idx = tid + j * NTH;             // 1024 x 16B
            int n = idx >> 3, seg = idx & 7;
            const __half* src = g_W + (size_t)(n0 + n) * K_SZ + kbase + seg * 8;
            uint32_t dst = bdst + SWZ(n * 128 + seg * 16);
            asm volatile("cp.async.cg.shared.global [%0], [%1], 16;" :: "r"(dst), "l"(src));
        }
        asm volatile("cp.async.commit_group;" ::: "memory");
    };

    auto gen_a = [&](int t) {                    // Z tile (sines) for k-tile t
        const int f = t & 63;
        const float w = __ldg(freqs + f);
        const float p = __ldg(phases + f);
        const uint32_t adst = sb + SM_A + (t & 1) * 16384;
        #pragma unroll
        for (int j = 0; j < 8; j++) {
            int g = tid + j * NTH;               // 2048 groups of 4 cols
            int m = g >> 4, kg = g & 15;
            float4 xv = *reinterpret_cast<const float4*>(smem + SM_X + m * 256 + kg * 16);
            float s0 = __sinf(fmaf(w, xv.x, p));
            float s1 = __sinf(fmaf(w, xv.y, p));
            float s2 = __sinf(fmaf(w, xv.z, p));
            float s3 = __sinf(fmaf(w, xv.w, p));
            __half2 h0 = __floats2half2_rn(s0, s1);
            __half2 h1 = __floats2half2_rn(s2, s3);
            uint32_t dst = adst + SWZ(m * 128 + kg * 8);
            asm volatile("st.shared.v2.b32 [%0], {%1, %2};"
                         :: "r"(dst), "r"(*(uint32_t*)&h0), "r"(*(uint32_t*)&h1));
        }
    };

    // ---- prologue ------------------------------------------------------
    load_x(0);
    __syncthreads();
    issue_b(0);
    gen_a(0);

    // ldmatrix lane-address components
    const int a_row = (lane & 15);                        // + wm + mt*16
    const int a_kb  = (lane >> 4) << 4;                   // + ks*32
    const int b_row = ((lane >> 4) << 3) + (lane & 7);    // + wn + np*16
    const int b_kb  = ((lane >> 3) & 1) << 4;             // + ks*32

    // ---- mainloop ------------------------------------------------------
    for (int t = 0; t < NITER; t++) {
        const int s = t & 1;
        asm volatile("cp.async.wait_group 0;" ::: "memory");
        __syncthreads();    // stage s fully ready; stage s^1 free

        if (((t + 1) & 63) == 0 && t + 1 < NITER) {   // new i-chunk
            load_x((t + 1) >> 6);
            __syncthreads();
        }
        if (t + 1 < NITER) {
            issue_b(t + 1);
            gen_a(t + 1);
        } else {
            asm volatile("cp.async.commit_group;" ::: "memory");
        }

        const uint32_t sA = sb + SM_A + s * 16384;
        const uint32_t sB = sb + SM_B + s * 16384;

        #pragma unroll
        for (int ks = 0; ks < 4; ks++) {
            uint32_t a[4][4], b[4][2];
            #pragma unroll
            for (int mt = 0; mt < 4; mt++) {
                uint32_t addr = sA + SWZ((wm + mt * 16 + a_row) * 128 + ks * 32 + a_kb);
                ldsm_x4(a[mt][0], a[mt][1], a[mt][2], a[mt][3], addr);
            }
            #pragma unroll
            for (int np = 0; np < 2; np++) {
                uint32_t addr = sB + SWZ((wn + np * 16 + b_row) * 128 + ks * 32 + b_kb);
                ldsm_x4(b[np * 2][0], b[np * 2][1], b[np * 2 + 1][0], b[np * 2 + 1][1], addr);
            }
            #pragma unroll
            for (int mt = 0; mt < 4; mt++)
                #pragma unroll
                for (int nt = 0; nt < 4; nt++)
                    mma16816(c[mt][nt], a[mt], b[nt]);
        }
    }

    // ---- epilogue ------------------------------------------------------
    const int r0 = lane >> 2;          // row within 16-row tile (0-7)
    const int c0 = (lane & 3) * 2;     // col pair within 8-col tile
    #pragma unroll
    for (int nt = 0; nt < 4; nt++) {
        const int col = n0 + wn + nt * 8 + c0;
        const float bz0 = __ldg(g_bias + col);
        const float bz1 = __ldg(g_bias + col + 1);
        #pragma unroll
        for (int mt = 0; mt < 4; mt++) {
            const int row = b0 + wm + mt * 16 + r0;
            float2 v0 = make_float2(c[mt][nt][0] + bz0, c[mt][nt][1] + bz1);
            float2 v1 = make_float2(c[mt][nt][2] + bz0, c[mt][nt][3] + bz1);
            *reinterpret_cast<float2*>(out + (size_t)row * O_SZ + col) = v0;
            *reinterpret_cast<float2*>(out + (size_t)(row + 8) * O_SZ + col) = v1;
        }
    }
}

// ---------------------------------------------------------------- launch
extern "C" void kernel_launch(void* const* d_in, const int* in_sizes, int n_in,
                              void* d_out, int out_size) {
    (void)in_sizes; (void)n_in; (void)out_size;
    const float* x      = (const float*)d_in[0];
    const float* freqs  = (const float*)d_in[1];
    const float* phases = (const float*)d_in[2];
    const float* beta   = (const float*)d_in[3];
    const float* lamb   = (const float*)d_in[4];
    const float* bias   = (const float*)d_in[5];
    float* out = (float*)d_out;

    prep_consts<<<1, 64>>>(freqs, phases);
    build_w<<<O_SZ, 256>>>(beta, lamb);
    build_bias<<<2, 256>>>(beta, lamb, bias);

    cudaFuncSetAttribute(act_gemm, cudaFuncAttributeMaxDynamicSharedMemorySize, SM_TOTAL);
    dim3 grid(O_SZ / BN, B_SZ / BM);  // (4, 64) = 256 CTAs, 2 per SM
    act_gemm<<<grid, NTH, SM_TOTAL>>>(x, freqs, phases, out);
}

// round 9
// speedup vs baseline: 1.0667x; 1.0033x over previous
#include <cuda_runtime.h>
#include <cuda_fp16.h>
#include <stdint.h>

// ============================================================================
// out[b,o] = sum_{i,f} norm(sin(w_f x[b,i] + p_f)) * beta[f,o] * lamb[i,o] + bias[o]
// == GEMM: Z[b,k] @ W[k,o],  k = f*512 + i
//   Z[b,k] = sin(w_f * x[b,i] + p_f)          (fp16, produced on the fly)
//   W[k,o] = a_f * beta[f,o] * lamb[i,o]      (fp16, precomputed once)
//   bias'[o] = bias[o] + (sum_f c_f beta[f,o]) * (sum_i lamb[i,o])
// R7: warp-specialized pipeline (R6 fixed).
//   Deadlock fix: no cp.async.mbarrier.arrive (its default form self-cancels:
//   +1 pending then arrive). Producer now does commit_group + wait_group 0
//   before ONE explicit arrive; full barrier expects 128 producer threads.
// ============================================================================

#define EPS_F 1e-3f
#define B_SZ 8192
#define I_SZ 512
#define F_SZ 64
#define O_SZ 512
#define K_SZ 32768

#define BM 128
#define BN 128
#define BK 64
#define NTH 384          // 256 consumer + 128 producer
#define NITER 512        // K_SZ / BK
#define NSTG 4

// SMEM: stage s: A at s*32768 (16KB), B at s*32768+16384 (16KB). 128KB total.
#define SM_STAGE(s) ((s) * 32768)
#define SM_BAR      131072            // 4 stages x (full,empty) x 8B
#define SM_TOTAL    131200

__device__ __half g_W[(size_t)O_SZ * K_SZ];   // [O][K], K contiguous (33.5 MB)
__device__ float  g_af[F_SZ];
__device__ float  g_cf[F_SZ];
__device__ float  g_bias[O_SZ];

#define SWZ(o) ((o) ^ (((o) >> 3) & 0x70))

__device__ __forceinline__ uint32_t smem_u32(const void* p) {
    return (uint32_t)__cvta_generic_to_shared(p);
}

__device__ __forceinline__ void ldsm_x4(uint32_t& r0, uint32_t& r1, uint32_t& r2,
                                        uint32_t& r3, uint32_t addr) {
    asm volatile("ldmatrix.sync.aligned.m8n8.x4.shared.b16 {%0,%1,%2,%3}, [%4];"
                 : "=r"(r0), "=r"(r1), "=r"(r2), "=r"(r3) : "r"(addr));
}

__device__ __forceinline__ void mma16816(float* c, const uint32_t* a, const uint32_t* b) {
    asm volatile(
        "mma.sync.aligned.m16n8k16.row.col.f32.f16.f16.f32 "
        "{%0,%1,%2,%3}, {%4,%5,%6,%7}, {%8,%9}, {%0,%1,%2,%3};"
        : "+f"(c[0]), "+f"(c[1]), "+f"(c[2]), "+f"(c[3])
        : "r"(a[0]), "r"(a[1]), "r"(a[2]), "r"(a[3]), "r"(b[0]), "r"(b[1]));
}

#define MBAR_INIT(addr, cnt) \
    asm volatile("mbarrier.init.shared.b64 [%0], %1;" :: "r"(addr), "r"(cnt) : "memory")
#define MBAR_ARRIVE(addr) \
    asm volatile("mbarrier.arrive.shared.b64 _, [%0];" :: "r"(addr) : "memory")

#define MBAR_WAIT(mbar, parity) do { \
    uint32_t _m = (uint32_t)(mbar); uint32_t _p = (uint32_t)(parity); uint32_t _d; \
    asm volatile( \
        "{\n\t.reg .pred p;\n\t" \
        "mbarrier.try_wait.parity.acquire.cta.shared::cta.b64 p, [%1], %2;\n\t" \
        "selp.b32 %0, 1, 0, p;\n\t}" \
        : "=r"(_d) : "r"(_m), "r"(_p) : "memory"); \
    if (!_d) { \
        asm volatile( \
            "{\n\t.reg .pred P1;\n\t" \
            "WL_%=:\n\t" \
            "mbarrier.try_wait.parity.acquire.cta.shared::cta.b64 P1, [%0], %1, 0x989680;\n\t" \
            "@P1 bra.uni WD_%=;\n\t" \
            "bra.uni WL_%=;\n\t" \
            "WD_%=:\n\t}" \
            :: "r"(_m), "r"(_p) : "memory"); \
    } \
} while (0)

// ---------------------------------------------------------------- precompute
__global__ void prep_consts(const float* __restrict__ freqs, const float* __restrict__ phases) {
    int f = threadIdx.x;
    if (f < F_SZ) {
        float w = freqs[f], p = phases[f];
        float mean = expf(-0.5f * w * w) * sinf(p);
        float var  = 0.5f - 0.5f * expf(-2.0f * w * w) * cosf(2.0f * p) - mean * mean;
        float inv  = rsqrtf(EPS_F + var);
        g_af[f] = inv;
        g_cf[f] = -mean * inv;
    }
}

__global__ void build_w(const float* __restrict__ beta, const float* __restrict__ lamb) {
    __shared__ float sl[I_SZ];
    __shared__ float sbv[F_SZ];
    int o = blockIdx.x;
    for (int i = threadIdx.x; i < I_SZ; i += blockDim.x) sl[i] = lamb[i * O_SZ + o];
    if (threadIdx.x < F_SZ)
        sbv[threadIdx.x] = g_af[threadIdx.x] * beta[threadIdx.x * O_SZ + o];
    __syncthreads();
    __half* wrow = g_W + (size_t)o * K_SZ;
    for (int k = threadIdx.x; k < K_SZ; k += blockDim.x) {
        int f = k >> 9, i = k & 511;
        wrow[k] = __float2half_rn(sbv[f] * sl[i]);
    }
}

__global__ void build_bias(const float* __restrict__ beta, const float* __restrict__ lamb,
                           const float* __restrict__ bias) {
    int o = blockIdx.x * blockDim.x + threadIdx.x;
    if (o < O_SZ) {
        float slm = 0.0f;
        for (int i = 0; i < I_SZ; i++) slm += lamb[i * O_SZ + o];
        float scb = 0.0f;
        for (int f = 0; f < F_SZ; f++) scb += g_cf[f] * beta[f * O_SZ + o];
        g_bias[o] = bias[o] + slm * scb;
    }
}

// ---------------------------------------------------------------- main GEMM
__global__ __launch_bounds__(NTH, 1)
void act_gemm(const float* __restrict__ x, const float* __restrict__ freqs,
              const float* __restrict__ phases, float* __restrict__ out) {
    extern __shared__ char smem[];
    const uint32_t sb = smem_u32(smem);
    const int tid  = threadIdx.x;
    const int wid  = tid >> 5;
    const int lane = tid & 31;

    const int n0 = blockIdx.x * BN;
    const int b0 = blockIdx.y * BM;

    // barriers: full[s] = SM_BAR + s*16 (count 128), empty[s] = +8 (count 256)
    if (tid == 0) {
        #pragma unroll
        for (int s = 0; s < NSTG; s++) {
            MBAR_INIT(sb + SM_BAR + s * 16, 128);
            MBAR_INIT(sb + SM_BAR + s * 16 + 8, 256);
        }
    }
    __syncthreads();

    if (wid >= 8) {
        // ================= PRODUCER (warps 8-11, ptid 0..127) =================
        const int ptid = tid - 256;
        const int mrow0 = ptid >> 4;          // A rows: mrow0 + j*8
        const int kg    = ptid & 15;          // A col group (4 fp16)
        const int bn0  = ptid >> 3;           // B rows: bn0 + j*16
        const int bseg = ptid & 7;            // B 16B segment

        float4 xr[16];

        for (int t = 0; t < NITER; t++) {
            const int s = t & (NSTG - 1);
            const int l = t >> 2;             // pipeline lap
            const int f = t & 63;
            const uint32_t full_b  = sb + SM_BAR + s * 16;
            const uint32_t empty_b = sb + SM_BAR + s * 16 + 8;

            if ((t & 63) == 0) {              // new i-chunk: x -> registers
                const int ic = t >> 6;
                const float* xs = x + (size_t)b0 * I_SZ + ic * BK + kg * 4;
                #pragma unroll
                for (int j = 0; j < 16; j++)
                    xr[j] = *reinterpret_cast<const float4*>(
                        xs + (size_t)(mrow0 + j * 8) * I_SZ);
            }

            if (l >= 1) MBAR_WAIT(empty_b, (l - 1) & 1);

            // ---- B tile: 8 x 16B cp.async per thread
            {
                const int kbase = f * I_SZ + (t >> 6) * BK;
                const uint32_t bdst = sb + SM_STAGE(s) + 16384;
                #pragma unroll
                for (int j = 0; j < 8; j++) {
                    const int n = bn0 + j * 16;
                    const __half* src = g_W + (size_t)(n0 + n) * K_SZ + kbase + bseg * 8;
                    uint32_t dst = bdst + SWZ(n * 128 + bseg * 16);
                    asm volatile("cp.async.cg.shared.global [%0], [%1], 16;"
                                 :: "r"(dst), "l"(src));
                }
                asm volatile("cp.async.commit_group;" ::: "memory");
            }

            // ---- A tile: 64 sines per thread (hides cp.async latency)
            {
                const float w = __ldg(freqs + f);
                const float p = __ldg(phases + f);
                const uint32_t adst = sb + SM_STAGE(s);
                #pragma unroll
                for (int j = 0; j < 16; j++) {
                    float s0 = __sinf(fmaf(w, xr[j].x, p));
                    float s1 = __sinf(fmaf(w, xr[j].y, p));
                    float s2 = __sinf(fmaf(w, xr[j].z, p));
                    float s3 = __sinf(fmaf(w, xr[j].w, p));
                    __half2 h0 = __floats2half2_rn(s0, s1);
                    __half2 h1 = __floats2half2_rn(s2, s3);
                    uint32_t dst = adst + SWZ((mrow0 + j * 8) * 128 + kg * 8);
                    asm volatile("st.shared.v2.b32 [%0], {%1, %2};"
                                 :: "r"(dst), "r"(*(uint32_t*)&h0), "r"(*(uint32_t*)&h1));
                }
            }

            // B copies done -> single arrive covers STS (release) + cp.async
            asm volatile("cp.async.wait_group 0;" ::: "memory");
            MBAR_ARRIVE(full_b);
        }
        return;
    }

    // ================= CONSUMER (warps 0-7) =================
    const int wm = (wid & 1) * 64;   // 2 M warp-rows
    const int wn = (wid >> 1) * 32;  // 4 N warp-cols

    float c[4][4][4];
    #pragma unroll
    for (int i = 0; i < 4; i++)
        #pragma unroll
        for (int j = 0; j < 4; j++)
            c[i][j][0] = c[i][j][1] = c[i][j][2] = c[i][j][3] = 0.0f;

    const int a_row = (lane & 15);
    const int a_kb  = (lane >> 4) << 4;
    const int b_row = ((lane >> 4) << 3) + (lane & 7);
    const int b_kb  = ((lane >> 3) & 1) << 4;

    for (int t = 0; t < NITER; t++) {
        const int s = t & (NSTG - 1);
        const int l = t >> 2;
        const uint32_t full_b  = sb + SM_BAR + s * 16;
        const uint32_t empty_b = sb + SM_BAR + s * 16 + 8;

        MBAR_WAIT(full_b, l & 1);

        const uint32_t sA = sb + SM_STAGE(s);
        const uint32_t sB = sA + 16384;

        #pragma unroll
        for (int ks = 0; ks < 4; ks++) {
            uint32_t a[4][4], b[4][2];
            #pragma unroll
            for (int mt = 0; mt < 4; mt++) {
                uint32_t addr = sA + SWZ((wm + mt * 16 + a_row) * 128 + ks * 32 + a_kb);
                ldsm_x4(a[mt][0], a[mt][1], a[mt][2], a[mt][3], addr);
            }
            #pragma unroll
            for (int np = 0; np < 2; np++) {
                uint32_t addr = sB + SWZ((wn + np * 16 + b_row) * 128 + ks * 32 + b_kb);
                ldsm_x4(b[np * 2][0], b[np * 2][1], b[np * 2 + 1][0], b[np * 2 + 1][1], addr);
            }
            #pragma unroll
            for (int mt = 0; mt < 4; mt++)
                #pragma unroll
                for (int nt = 0; nt < 4; nt++)
                    mma16816(c[mt][nt], a[mt], b[nt]);
        }

        MBAR_ARRIVE(empty_b);
    }

    // ---- epilogue ------------------------------------------------------
    const int r0 = lane >> 2;
    const int c0 = (lane & 3) * 2;
    #pragma unroll
    for (int nt = 0; nt < 4; nt++) {
        const int col = n0 + wn + nt * 8 + c0;
        const float bz0 = __ldg(g_bias + col);
        const float bz1 = __ldg(g_bias + col + 1);
        #pragma unroll
        for (int mt = 0; mt < 4; mt++) {
            const int row = b0 + wm + mt * 16 + r0;
            float2 v0 = make_float2(c[mt][nt][0] + bz0, c[mt][nt][1] + bz1);
            float2 v1 = make_float2(c[mt][nt][2] + bz0, c[mt][nt][3] + bz1);
            *reinterpret_cast<float2*>(out + (size_t)row * O_SZ + col) = v0;
            *reinterpret_cast<float2*>(out + (size_t)(row + 8) * O_SZ + col) = v1;
        }
    }
}

// ---------------------------------------------------------------- launch
extern "C" void kernel_launch(void* const* d_in, const int* in_sizes, int n_in,
                              void* d_out, int out_size) {
    (void)in_sizes; (void)n_in; (void)out_size;
    const float* x      = (const float*)d_in[0];
    const float* freqs  = (const float*)d_in[1];
    const float* phases = (const float*)d_in[2];
    const float* beta   = (const float*)d_in[3];
    const float* lamb   = (const float*)d_in[4];
    const float* bias   = (const float*)d_in[5];
    float* out = (float*)d_out;

    prep_consts<<<1, 64>>>(freqs, phases);
    build_w<<<O_SZ, 256>>>(beta, lamb);
    build_bias<<<2, 256>>>(beta, lamb, bias);

    cudaFuncSetAttribute(act_gemm, cudaFuncAttributeMaxDynamicSharedMemorySize, SM_TOTAL);
    dim3 grid(O_SZ / BN, B_SZ / BM);  // (4, 64) = 256 CTAs
    act_gemm<<<grid, NTH, SM_TOTAL>>>(x, freqs, phases, out);
}